// round 13
// baseline (speedup 1.0000x reference)
#include <cuda_runtime.h>
#include <cuda_fp16.h>
#include <cstdint>

// ============================================================================
// RBFEuclidean: out[b,u] = ||x_b||^2 - 2 x@w + ||w_u||^2
// x: [65536,256] f32, w: [256,1024] f32, out: [65536,1024] f32
//
// classic mma.sync, compute_103-safe.
// R13: R12 skeleton (2 CTAs/SM, [64k x 128n] phases, m32n64 warp tile, one
// sync/phase, direct-STG epilogue) + fp16 ACCUMULATION in two independent
// chains (even/odd k16, each K=128), combined in f32 at the epilogue.
// f32-acc HMMA measured rt~12/SMSP => at 70% of its ceiling; fp16 acc
// doubles the pipe rate.
// ============================================================================

#define THREADS 256
#define MTILE   128
#define KTOT    256
#define NPHASE  32            // 8 n-tiles x 4 k-quarters

#define OFF_XSQ    0              // 128 f32 -> 512
#define OFF_WSQ    512            // 1024 f32 -> 4608
#define OFF_A      5120           // 128 rows * 512B = 65536 -> 70656
#define OFF_B      70656          // 2 * 16384 -> 103424
#define BBUF_BYTES 16384
#define SMEM_BYTES 103424

__device__ __half g_w16[256 * 1024];   // w as [k][n], fp16
__device__ float  g_wsq[1024];

// ---------------------------------------------------------------------------
__device__ __forceinline__ void cp_async16(uint32_t smem_addr, const void* gptr) {
    asm volatile("cp.async.cg.shared.global [%0], [%1], 16;"
                 :: "r"(smem_addr), "l"(__cvta_generic_to_global(gptr)) : "memory");
}
__device__ __forceinline__ void cp_commit() {
    asm volatile("cp.async.commit_group;" ::: "memory");
}
template <int N>
__device__ __forceinline__ void cp_wait() {
    asm volatile("cp.async.wait_group %0;" :: "n"(N) : "memory");
}

__device__ __forceinline__ void ldsm_x4(uint32_t* r, uint32_t addr) {
    asm volatile("ldmatrix.sync.aligned.m8n8.x4.shared.b16 {%0,%1,%2,%3}, [%4];"
                 : "=r"(r[0]), "=r"(r[1]), "=r"(r[2]), "=r"(r[3]) : "r"(addr));
}
__device__ __forceinline__ void ldsm_x4_t(uint32_t* r, uint32_t addr) {
    asm volatile("ldmatrix.sync.aligned.m8n8.x4.trans.shared.b16 {%0,%1,%2,%3}, [%4];"
                 : "=r"(r[0]), "=r"(r[1]), "=r"(r[2]), "=r"(r[3]) : "r"(addr));
}
// fp16-accumulate HMMA: D (f16x2 x2) = A*B + D
__device__ __forceinline__ void mma16816_f16(uint32_t* d, const uint32_t* a, const uint32_t* b) {
    asm volatile(
        "mma.sync.aligned.m16n8k16.row.col.f16.f16.f16.f16 "
        "{%0,%1}, {%2,%3,%4,%5}, {%6,%7}, {%0,%1};"
        : "+r"(d[0]), "+r"(d[1])
        : "r"(a[0]), "r"(a[1]), "r"(a[2]), "r"(a[3]), "r"(b[0]), "r"(b[1]));
}

// ---------------------------------------------------------------------------
// Prep: w -> fp16 copy + w_sq (f32). 64 blocks x 256 threads.
// ---------------------------------------------------------------------------
__global__ void prep_w_kernel(const float* __restrict__ w) {
    int t = blockIdx.x * 256 + threadIdx.x;      // 0..16383
#pragma unroll
    for (int i = 0; i < 16; i++) {
        int idx = t + i * 16384;
        g_w16[idx] = __float2half(w[idx]);
    }
    if (t < 1024) {
        float acc = 0.f;
#pragma unroll 8
        for (int f = 0; f < 256; f++) {
            float v = w[(size_t)f * 1024 + t];
            acc += v * v;
        }
        g_wsq[t] = acc;
    }
}

// ---------------------------------------------------------------------------
// B stage prefetch: stage s covers cols (s>>2)*128.., k-rows (s&3)*64..
// Buffer layout: 64 k-rows x 256B (128 cols fp16), 16B-chunk swizzle.
// ---------------------------------------------------------------------------
__device__ __forceinline__ void prefetch_b(uint32_t sb, int s, int tid) {
    const int nt = s >> 2, kq = s & 3;
    const uint32_t bufbase = sb + OFF_B + (uint32_t)((s & 1) * BBUF_BYTES);
#pragma unroll
    for (int i = 0; i < 4; i++) {
        int idx = tid + i * 256;              // 0..1023 16B chunks
        int k = idx >> 4, c = idx & 15;       // k-row 0..63, chunk 0..15
        const __half* src = g_w16 + (size_t)(kq * 64 + k) * 1024 + nt * 128 + c * 8;
        uint32_t dst = bufbase + k * 256 + ((c ^ (k & 7)) << 4);
        cp_async16(dst, src);
    }
    cp_commit();
}

// ---------------------------------------------------------------------------
// Main kernel: 512 CTAs x 256 threads, 2 CTAs/SM.
// ---------------------------------------------------------------------------
__global__ void __launch_bounds__(THREADS, 2)
rbf_main_kernel(const float* __restrict__ x, float* __restrict__ out) {
    extern __shared__ char smem[];
    const uint32_t sb = (uint32_t)__cvta_generic_to_shared(smem);
    const int tid = threadIdx.x;
    const int wid = tid >> 5;
    const int lid = tid & 31;
    const int wm = wid >> 1;          // m-warp 0..3 (32 rows each)
    const int wn = wid & 1;           // n-warp 0..1 (64 cols each)
    const size_t m_base = (size_t)blockIdx.x * MTILE;

    // --- prefetch B stage 0 ---
    prefetch_b(sb, 0, tid);

    // --- w_sq to smem ---
    {
        float* wsq_s = (float*)(smem + OFF_WSQ);
#pragma unroll
        for (int i = 0; i < 4; i++) wsq_s[tid + i * 256] = g_wsq[tid + i * 256];
    }

    // --- A load: f32 -> fp16 swizzled smem, x_sq in f32 (8 threads/row) ---
    {
        const int lo = tid & 7;
        const int rq = tid >> 3;              // 0..31
        const float4* xv = (const float4*)(x + m_base * KTOT);
        float* xsq_s = (float*)(smem + OFF_XSQ);
#pragma unroll 1
        for (int pass = 0; pass < 4; pass++) {
            int r = pass * 32 + rq;
            int rx = r & 7;
            uint32_t rowbase = (uint32_t)(OFF_A + r * 512);
            float acc = 0.f;
#pragma unroll
            for (int j = 0; j < 8; j++) {
                int c4 = lo + j * 8;          // float4 index 0..63
                float4 v = xv[(size_t)r * 64 + c4];
                acc += v.x * v.x + v.y * v.y + v.z * v.z + v.w * v.w;
                __half2 h0 = __floats2half2_rn(v.x, v.y);
                __half2 h1 = __floats2half2_rn(v.z, v.w);
                uint32_t byte = rowbase + ((uint32_t)((c4 >> 1) ^ rx) << 4) + ((c4 & 1) << 3);
                uint2 u;
                u.x = *(uint32_t*)&h0;
                u.y = *(uint32_t*)&h1;
                *(uint2*)(smem + byte) = u;
            }
            acc += __shfl_xor_sync(0xffffffffu, acc, 1);
            acc += __shfl_xor_sync(0xffffffffu, acc, 2);
            acc += __shfl_xor_sync(0xffffffffu, acc, 4);
            if (lo == 0) xsq_s[r] = acc;
        }
    }

    const float* xsq_s = (const float*)(smem + OFF_XSQ);
    const float* wsq_s = (const float*)(smem + OFF_WSQ);

    // A addressing: rows wm*32 + (lid&15), +16
    const uint32_t aaddr0 = sb + OFF_A + (uint32_t)(wm * 32 + (lid & 15)) * 512;
    const uint32_t aaddr1 = aaddr0 + 16 * 512;
    const int ahi = lid >> 4;
    const int asw = lid & 7;

    // B ldsm offsets: 4 ldsm_x4_t cover n64 (n8 tiles wn*8 .. wn*8+7)
    uint32_t bofs[4];
    {
        int sub = lid >> 3;
#pragma unroll
        for (int q = 0; q < 4; q++) {
            int jl = wn * 8 + 2 * q + (sub >> 1);
            bofs[q] = (uint32_t)((sub & 1) * 2048 + (lid & 7) * 256 + ((jl ^ (lid & 7)) << 4));
        }
    }

    // publish stage 0, issue stage 1
    cp_wait<0>();
    __syncthreads();
    prefetch_b(sb, 1, tid);

    // Two independent fp16 accumulator chains (even/odd k16 steps)
    uint32_t dA[2][8][2], dB[2][8][2];

    for (int p = 0; p < NPHASE; p++) {
        const int kq = p & 3;
        if (kq == 0) {
#pragma unroll
            for (int mt = 0; mt < 2; mt++)
#pragma unroll
                for (int j = 0; j < 8; j++) {
                    dA[mt][j][0] = 0u; dA[mt][j][1] = 0u;
                    dB[mt][j][0] = 0u; dB[mt][j][1] = 0u;
                }
        }

        const uint32_t bbase = sb + OFF_B + (uint32_t)((p & 1) * BBUF_BYTES);

#pragma unroll
        for (int ksl = 0; ksl < 4; ksl++) {
            const int ks = kq * 4 + ksl;     // global k16 index for A
            uint32_t a[2][4];
            uint32_t swz = (uint32_t)((2 * ks + ahi) ^ asw) << 4;
            ldsm_x4(a[0], aaddr0 + swz);
            ldsm_x4(a[1], aaddr1 + swz);
            uint32_t b[8][2];
#pragma unroll
            for (int q = 0; q < 4; q++) {
                uint32_t r4[4];
                ldsm_x4_t(r4, bbase + (uint32_t)ksl * 4096 + bofs[q]);
                b[2 * q][0] = r4[0];
                b[2 * q][1] = r4[1];
                b[2 * q + 1][0] = r4[2];
                b[2 * q + 1][1] = r4[3];
            }
            if (ksl & 1) {
#pragma unroll
                for (int mt = 0; mt < 2; mt++)
#pragma unroll
                    for (int j = 0; j < 8; j++)
                        mma16816_f16(dB[mt][j], a[mt], b[j]);
            } else {
#pragma unroll
                for (int mt = 0; mt < 2; mt++)
#pragma unroll
                    for (int j = 0; j < 8; j++)
                        mma16816_f16(dA[mt][j], a[mt], b[j]);
            }
        }

        if (kq == 3) {
            // --- epilogue: combine chains in f32, direct STG.64 ---
            const int col0 = (p >> 2) * 128 + wn * 64;
            const int cb = (lid & 3) * 2;
            float2 wq[8];
#pragma unroll
            for (int j = 0; j < 8; j++)
                wq[j] = *(const float2*)(wsq_s + col0 + j * 8 + cb);
#pragma unroll
            for (int mt = 0; mt < 2; mt++)
#pragma unroll
                for (int h = 0; h < 2; h++) {
                    int grow = wm * 32 + mt * 16 + h * 8 + (lid >> 2);
                    float xs = xsq_s[grow];
                    float* orow = out + (m_base + grow) * 1024 + col0 + cb;
#pragma unroll
                    for (int j = 0; j < 8; j++) {
                        float2 fa = __half22float2(*(const __half2*)&dA[mt][j][h]);
                        float2 fb = __half22float2(*(const __half2*)&dB[mt][j][h]);
                        float2 o;
                        o.x = fmaf(-2.f, fa.x + fb.x, xs + wq[j].x);
                        o.y = fmaf(-2.f, fa.y + fb.y, xs + wq[j].y);
                        *(float2*)(orow + j * 8) = o;
                    }
                }
        }

        if (p + 1 < NPHASE) {
            cp_wait<0>();        // stage p+1 (issued a full phase ago) complete
            __syncthreads();     // publish stage p+1; all reads of buf[p&1] done
            if (p + 2 < NPHASE)
                prefetch_b(sb, p + 2, tid);   // into just-freed buf[p&1]
        }
    }
}

// ---------------------------------------------------------------------------
extern "C" void kernel_launch(void* const* d_in, const int* in_sizes, int n_in,
                              void* d_out, int out_size) {
    (void)in_sizes; (void)n_in; (void)out_size;
    const float* x = (const float*)d_in[0];
    const float* w = (const float*)d_in[1];
    float* out = (float*)d_out;

    cudaFuncSetAttribute(rbf_main_kernel,
                         cudaFuncAttributeMaxDynamicSharedMemorySize, SMEM_BYTES);

    prep_w_kernel<<<64, 256>>>(w);
    rbf_main_kernel<<<512, THREADS, SMEM_BYTES>>>(x, out);
}